// round 8
// baseline (speedup 1.0000x reference)
#include <cuda_runtime.h>
#include <cuda_bf16.h>
#include <math.h>

#define NS   25      // n_shot * n_way (support samples)
#define NW   5       // n_way
#define NV   125     // QP variables
#define DIM  640
#define NQ   75
#define MAXB 512
#define TQP  160     // 5 warps for k_qp
#define HD   320     // dim chunk for k_prep

// ------------------- global scratch (static, no allocations) -------------------
__device__ float g_ftu[(size_t)MAXB * NS * DIM];     // transformed (unnormalized) train feats
__device__ float g_Kp[(size_t)2 * MAXB * NS * NS];   // partial raw Gram (per dim-chunk)
__device__ float g_W[(size_t)MAXB * NW * DIM];       // SVM weights per batch

// ------------------- simple_transform -------------------
__device__ __forceinline__ float simp_g(float u) {
    float t = __logf(__fdividef(1.0f, u + 1e-5f) + 1.0f);
    return __powf(t, -1.3f);
}
// f(x) = sign(x) * (g(|x|) - g(0)) == pos+neg of the reference
__device__ __forceinline__ float simp(float x, float c0) {
    float g = simp_g(fabsf(x));
    return (x >= 0.0f) ? (g - c0) : (c0 - g);
}

// =====================================================================
// Kernel 1: transform train chunk, partial raw Gram via warp-per-pair f4 dots
// grid = 2*B  (blockIdx.x = b*2 + chunk)
// =====================================================================
__global__ void __launch_bounds__(256) k_prep(const float* __restrict__ ftrain,
                                              const int* __restrict__ usp) {
    __shared__ __align__(16) float tile[NS * HD];   // 32 KB
    int bb = blockIdx.x, b = bb >> 1, ch = bb & 1;
    int tid = threadIdx.x;
    int us = usp ? (usp[0] != 0) : 1;
    float c0 = simp_g(0.0f);

    const float* fb = ftrain + (size_t)b * NS * DIM + ch * HD;
    float* fo = g_ftu + (size_t)b * NS * DIM + ch * HD;

    for (int e = tid; e < NS * HD; e += 256) {
        int r = e / HD, c = e - r * HD;
        float v = fb[r * DIM + c];
        if (us) v = simp(v, c0);
        tile[e] = v;
        fo[r * DIM + c] = v;
    }
    __syncthreads();

    int wp = tid >> 5, ln = tid & 31;
    float* Kout = g_Kp + ((size_t)ch * MAXB + b) * (NS * NS);
    for (int p = wp; p < 325; p += 8) {
        // map linear upper-tri index -> (r, c), warp-uniform
        int r = 0, rem = p;
        while (rem >= NS - r) { rem -= NS - r; r++; }
        int c = r + rem;
        const float4* A4 = (const float4*)(tile + r * HD);
        const float4* B4 = (const float4*)(tile + c * HD);
        // 80 float4 per row: lanes cover {ln, ln+32, ln+64(<80)}
        float4 a0 = A4[ln],      v0 = B4[ln];
        float4 a1 = A4[ln + 32], v1 = B4[ln + 32];
        float acc = a0.x * v0.x;
        acc = fmaf(a0.y, v0.y, acc); acc = fmaf(a0.z, v0.z, acc); acc = fmaf(a0.w, v0.w, acc);
        acc = fmaf(a1.x, v1.x, acc); acc = fmaf(a1.y, v1.y, acc);
        acc = fmaf(a1.z, v1.z, acc); acc = fmaf(a1.w, v1.w, acc);
        if (ln < 16) {
            float4 a2 = A4[ln + 64], v2 = B4[ln + 64];
            acc = fmaf(a2.x, v2.x, acc); acc = fmaf(a2.y, v2.y, acc);
            acc = fmaf(a2.z, v2.z, acc); acc = fmaf(a2.w, v2.w, acc);
        }
        #pragma unroll
        for (int o = 16; o; o >>= 1) acc += __shfl_down_sync(0xffffffffu, acc, o);
        if (ln == 0) {
            Kout[r * NS + c] = acc;
            if (c != r) Kout[c * NS + r] = acc;
        }
    }
}

// =====================================================================
// Kernel 2: QP via IPM — one CTA (5 warps) per batch element, + W epilogue
// =====================================================================
struct QPShared {
    float M[625];
    float Hinv[NW][625];   // cholesky workspace -> becomes H_w^{-1}
    float Bbuf[NW][625];   // L^{-1} scratch
    float Smat[625];       // S_y, chol'ed in place
    float SB[625];         // L_S^{-1}
    float Sinv[625];
    float x[NV], s_[NV], z_[NV], bestx[NV], d_[NV];
    float rx[NV], rz[NV], r1[NV], uv[NV], rsc[NV];
    float dxa[NV], dsa[NV], dza[NV];
    float dxc[NV], dsc[NV], dzc[NV];
    float y_[NS], ry[NS], gvec[NS], dya[NS], dyc[NS];
    float inv[NS];
    float red[8];
};

__device__ __forceinline__ float blk_sum5(float v, volatile float* red) {
    int tid = threadIdx.x;
    __syncthreads();
    #pragma unroll
    for (int o = 16; o; o >>= 1) v += __shfl_down_sync(0xffffffffu, v, o);
    if ((tid & 31) == 0) red[tid >> 5] = v;
    __syncthreads();
    return red[0] + red[1] + red[2] + red[3] + red[4];
}
__device__ __forceinline__ float blk_min5(float v, volatile float* red) {
    int tid = threadIdx.x;
    __syncthreads();
    #pragma unroll
    for (int o = 16; o; o >>= 1) v = fminf(v, __shfl_down_sync(0xffffffffu, v, o));
    if ((tid & 31) == 0) red[tid >> 5] = v;
    __syncthreads();
    return fminf(fminf(fminf(red[0], red[1]), fminf(red[2], red[3])), red[4]);
}

// warp-cooperative 25x25 Cholesky (in place, lower)
__device__ void chol25(float* A, int ln) {
    for (int j = 0; j < NS; j++) {
        float Ajj = A[j * NS + j];
        __syncwarp();
        float Ljj = sqrtf(Ajj);
        float inv = 1.0f / Ljj;
        if (ln == j) A[j * NS + j] = Ljj;
        else if (ln > j && ln < NS) A[ln * NS + j] *= inv;
        __syncwarp();
        if (ln > j && ln < NS) {
            float Lij = A[ln * NS + j];
            for (int k = j + 1; k <= ln; k++)
                A[ln * NS + k] = fmaf(-Lij, A[k * NS + j], A[ln * NS + k]);
        }
        __syncwarp();
    }
}
// B = L^{-1} (lane = column); only lower triangle written/used downstream
__device__ void trinv25(const float* L, float* B, int ln) {
    if (ln < NS) {
        int j = ln;
        B[j * NS + j] = 1.0f / L[j * NS + j];
        for (int i = j + 1; i < NS; i++) {
            float ssum = 0.0f;
            for (int k = j; k < i; k++) ssum = fmaf(L[i * NS + k], B[k * NS + j], ssum);
            B[i * NS + j] = -ssum / L[i * NS + i];
        }
    }
    __syncwarp();
}
// Out = B^T B  (= (L L^T)^{-1}); lane = row; reads only lower of B
__device__ void ltl25(const float* B, float* Out, int ln) {
    if (ln < NS) {
        int i = ln;
        for (int j = 0; j < NS; j++) {
            int k0 = (i > j) ? i : j;
            float acc = 0.0f;
            for (int k = k0; k < NS; k++) acc = fmaf(B[k * NS + i], B[k * NS + j], acc);
            Out[i * NS + j] = acc;
        }
    }
    __syncwarp();
}

__device__ void factorize(QPShared& S) {
    int tid = threadIdx.x, wp = tid >> 5, ln = tid & 31;
    float* A = S.Hinv[wp];
    for (int e = ln; e < 625; e += 32) {
        int i = e / NS, j = e - i * NS;
        float v = S.M[e];
        if (i == j) v += S.d_[i * NW + wp];
        A[e] = v;
    }
    __syncwarp();
    chol25(A, ln);
    trinv25(A, S.Bbuf[wp], ln);
    ltl25(S.Bbuf[wp], A, ln);                 // A = H_w^{-1}
    __syncthreads();
    for (int e = tid; e < 625; e += TQP)
        S.Smat[e] = S.Hinv[0][e] + S.Hinv[1][e] + S.Hinv[2][e] + S.Hinv[3][e] + S.Hinv[4][e];
    __syncthreads();
    if (wp == 0) {
        chol25(S.Smat, ln);
        trinv25(S.Smat, S.SB, ln);
        ltl25(S.SB, S.Sinv, ln);
    }
    __syncthreads();
}

// KKT apply: NULL pointer == zero vector
__device__ void applyKKT(QPShared& S, const float* rx, const float* rs,
                         const float* rz, const float* ry,
                         float* dx, float* ds, float* dz, float* dy) {
    int tid = threadIdx.x, wp = tid >> 5, ln = tid & 31;
    if (tid < NV) {
        float rxv = rx ? rx[tid] : 0.0f;
        float rsv = rs ? rs[tid] : 0.0f;
        float rzv = rz ? rz[tid] : 0.0f;
        S.r1[tid] = -rxv - S.d_[tid] * rzv + rsv;
    }
    __syncthreads();
    if (ln < NS) {                      // u_w = H_w^{-1} r1_w
        const float* Hi = S.Hinv[wp] + ln * NS;
        float acc = 0.0f;
        #pragma unroll
        for (int j = 0; j < NS; j++) acc = fmaf(Hi[j], S.r1[j * NW + wp], acc);
        S.uv[ln * NW + wp] = acc;
    }
    __syncthreads();
    if (tid < NS) {
        float g = S.uv[tid * NW] + S.uv[tid * NW + 1] + S.uv[tid * NW + 2]
                + S.uv[tid * NW + 3] + S.uv[tid * NW + 4];
        if (ry) g += ry[tid];
        S.gvec[tid] = g;
    }
    __syncthreads();
    if (wp == 0 && ln < NS) {           // dy = S_y^{-1} g
        const float* Si = S.Sinv + ln * NS;
        float acc = 0.0f;
        #pragma unroll
        for (int j = 0; j < NS; j++) acc = fmaf(Si[j], S.gvec[j], acc);
        dy[ln] = acc;
    }
    __syncthreads();
    if (ln < NS) {                      // dx = u - H^{-1} A^T dy
        const float* Hi = S.Hinv[wp] + ln * NS;
        float acc = 0.0f;
        #pragma unroll
        for (int j = 0; j < NS; j++) acc = fmaf(Hi[j], dy[j], acc);
        dx[ln * NW + wp] = S.uv[ln * NW + wp] - acc;
    }
    __syncthreads();
    if (tid < NV) {
        float rsv = rs ? rs[tid] : 0.0f;
        float rzv = rz ? rz[tid] : 0.0f;
        float dxv = dx[tid];
        dz[tid] = S.d_[tid] * (dxv + rzv) - rsv;
        ds[tid] = -dxv - rzv;
    }
    __syncthreads();
}

__global__ void __launch_bounds__(TQP) k_qp() {
    __shared__ QPShared S;
    int b = blockIdx.x, tid = threadIdx.x;
    // sum partial raw Gram
    for (int e = tid; e < 625; e += TQP)
        S.M[e] = g_Kp[(size_t)b * 625 + e] + g_Kp[((size_t)MAXB + b) * 625 + e];
    __syncthreads();
    if (tid < NS)
        S.inv[tid] = 1.0f / fmaxf(sqrtf(S.M[tid * NS + tid]), 1e-12f);
    __syncthreads();
    for (int e = tid; e < 625; e += TQP) {
        int r = e / NS, c = e - r * NS;
        S.M[e] = S.M[e] * S.inv[r] * S.inv[c] + ((r == c) ? 1.0f : 0.0f);
    }
    if (tid < NV) {
        S.d_[tid] = 1.0f;
        int sidx = tid / NW, w = tid - sidx * NW;
        float oh = ((sidx % NW) == w) ? 1.0f : 0.0f;
        S.rx[tid] = -oh;          // p
        S.rz[tid] = -0.1f * oh;   // -h
    }
    __syncthreads();
    factorize(S);
    applyKKT(S, S.rx, nullptr, S.rz, nullptr, S.x, S.s_, S.z_, S.y_);
    // shift s, z
    float mv = (tid < NV) ? S.s_[tid] : 3.0e38f;
    float m = blk_min5(mv, S.red);
    if (tid < NV && m < 0.0f) S.s_[tid] -= (m - 1.0f);
    mv = (tid < NV) ? S.z_[tid] : 3.0e38f;
    m = blk_min5(mv, S.red);
    if (tid < NV && m < 0.0f) S.z_[tid] -= (m - 1.0f);
    __syncthreads();

    float best_res = 3.0e38f;
    int wp = tid >> 5, ln = tid & 31;
    for (int it = 0; it < 3; it++) {
        // residuals
        if (ln < NS) {
            const float* Mr = S.M + ln * NS;
            float qx = 0.0f;
            #pragma unroll
            for (int j = 0; j < NS; j++) qx = fmaf(Mr[j], S.x[j * NW + wp], qx);
            int v = ln * NW + wp;
            float oh = ((ln % NW) == wp) ? 1.0f : 0.0f;
            S.rx[v] = S.y_[ln] + S.z_[v] + qx - oh;
            S.rz[v] = S.x[v] + S.s_[v] - 0.1f * oh;
        }
        if (tid < NS)
            S.ry[tid] = S.x[tid * NW] + S.x[tid * NW + 1] + S.x[tid * NW + 2]
                      + S.x[tid * NW + 3] + S.x[tid * NW + 4];
        float szv = (tid < NV) ? S.s_[tid] * S.z_[tid] : 0.0f;
        float sz = blk_sum5(szv, S.red);          // also barriers the writes above
        float mu = fabsf(sz) * (1.0f / 125.0f);
        float t2 = (tid < NV) ? S.rx[tid] * S.rx[tid] : 0.0f;
        float nrx = sqrtf(blk_sum5(t2, S.red) + 1e-30f);
        t2 = (tid < NV) ? S.rz[tid] * S.rz[tid] : 0.0f;
        float nrz = sqrtf(blk_sum5(t2, S.red) + 1e-30f);
        t2 = (tid < NS) ? S.ry[tid] * S.ry[tid] : 0.0f;
        float nry = sqrtf(blk_sum5(t2, S.red) + 1e-30f);
        float res = nrz + nry + nrx + 125.0f * mu;
        if (res < best_res) { best_res = res; if (tid < NV) S.bestx[tid] = S.x[tid]; }
        if (it == 2) break;

        if (tid < NV) S.d_[tid] = S.z_[tid] / S.s_[tid];
        __syncthreads();
        factorize(S);
        // affine
        applyKKT(S, S.rx, S.z_, S.rz, S.ry, S.dxa, S.dsa, S.dza, S.dya);
        float az = (tid < NV) ? ((S.dza[tid] < 0.0f) ? -S.z_[tid] / S.dza[tid] : 1e12f) : 1e12f;
        float as = (tid < NV) ? ((S.dsa[tid] < 0.0f) ? -S.s_[tid] / S.dsa[tid] : 1e12f) : 1e12f;
        float alpha = fminf(blk_min5(fminf(az, as), S.red), 1.0f);
        float tt = (tid < NV) ? (S.s_[tid] + alpha * S.dsa[tid]) * (S.z_[tid] + alpha * S.dza[tid]) : 0.0f;
        float sumt = blk_sum5(tt, S.red);
        float ratio = sumt / sz;
        float musig = mu * ratio * ratio * ratio;
        if (tid < NV) S.rsc[tid] = (-musig + S.dsa[tid] * S.dza[tid]) / S.s_[tid];
        __syncthreads();
        // corrector
        applyKKT(S, nullptr, S.rsc, nullptr, nullptr, S.dxc, S.dsc, S.dzc, S.dyc);
        if (tid < NV) { S.dxa[tid] += S.dxc[tid]; S.dsa[tid] += S.dsc[tid]; S.dza[tid] += S.dzc[tid]; }
        if (tid < NS) S.dya[tid] += S.dyc[tid];
        __syncthreads();
        az = (tid < NV) ? ((S.dza[tid] < 0.0f) ? -S.z_[tid] / S.dza[tid] : 1e12f) : 1e12f;
        as = (tid < NV) ? ((S.dsa[tid] < 0.0f) ? -S.s_[tid] / S.dsa[tid] : 1e12f) : 1e12f;
        alpha = fminf(0.999f * blk_min5(fminf(az, as), S.red), 1.0f);
        if (tid < NV) {
            S.x[tid]  += alpha * S.dxa[tid];
            S.s_[tid] += alpha * S.dsa[tid];
            S.z_[tid] += alpha * S.dza[tid];
        }
        if (tid < NS) S.y_[tid] += alpha * S.dya[tid];
        __syncthreads();
    }
    // ---- epilogue: W = (bestx * invn)^T ftu  (5 x 640) ----
    if (tid < NV) S.x[tid] = S.bestx[tid] * S.inv[tid / NW];
    __syncthreads();
    const float* fu = g_ftu + (size_t)b * NS * DIM;
    float* Wo = g_W + (size_t)b * (NW * DIM);
    for (int dd = tid; dd < DIM; dd += TQP) {
        float a0 = 0, a1 = 0, a2 = 0, a3 = 0, a4 = 0;
        #pragma unroll
        for (int s = 0; s < NS; s++) {
            float fv = fu[s * DIM + dd];
            a0 = fmaf(S.x[s * NW + 0], fv, a0);
            a1 = fmaf(S.x[s * NW + 1], fv, a1);
            a2 = fmaf(S.x[s * NW + 2], fv, a2);
            a3 = fmaf(S.x[s * NW + 3], fv, a3);
            a4 = fmaf(S.x[s * NW + 4], fv, a4);
        }
        Wo[0 * DIM + dd] = a0; Wo[1 * DIM + dd] = a1; Wo[2 * DIM + dd] = a2;
        Wo[3 * DIM + dd] = a3; Wo[4 * DIM + dd] = a4;
    }
}

// =====================================================================
// Kernel 3: out[q,w] = <W_w, t(fq_q)> / ||t(fq_q)||, float4 path
// grid = 3*B, 25 queries per CTA
// =====================================================================
__global__ void __launch_bounds__(256) k_out(const float* __restrict__ ftest,
                                             const int* __restrict__ usp,
                                             float* __restrict__ out) {
    __shared__ __align__(16) float W[NW * DIM];
    int bb = blockIdx.x, b = bb / 3, part = bb - b * 3;
    int tid = threadIdx.x;
    int us = usp ? (usp[0] != 0) : 1;
    float c0 = simp_g(0.0f);
    for (int e = tid; e < NW * DIM; e += 256) W[e] = g_W[(size_t)b * NW * DIM + e];
    __syncthreads();
    int wp = tid >> 5, ln = tid & 31;
    const float* fq = ftest + (size_t)b * NQ * DIM;
    int q0 = part * 25;
    for (int q = q0 + wp; q < q0 + 25; q += 8) {
        const float4* row4 = (const float4*)(fq + (size_t)q * DIM);
        float ss = 0, d0 = 0, d1 = 0, d2 = 0, d3 = 0, d4 = 0;
        #pragma unroll
        for (int j = 0; j < 5; j++) {
            int i4 = ln + 32 * j;                 // 160 float4 per row
            float4 v = row4[i4];
            if (us) {
                v.x = simp(v.x, c0); v.y = simp(v.y, c0);
                v.z = simp(v.z, c0); v.w = simp(v.w, c0);
            }
            ss = fmaf(v.x, v.x, fmaf(v.y, v.y, fmaf(v.z, v.z, fmaf(v.w, v.w, ss))));
            float4 w0 = ((const float4*)(W + 0 * DIM))[i4];
            float4 w1 = ((const float4*)(W + 1 * DIM))[i4];
            float4 w2 = ((const float4*)(W + 2 * DIM))[i4];
            float4 w3 = ((const float4*)(W + 3 * DIM))[i4];
            float4 w4 = ((const float4*)(W + 4 * DIM))[i4];
            d0 = fmaf(w0.x, v.x, fmaf(w0.y, v.y, fmaf(w0.z, v.z, fmaf(w0.w, v.w, d0))));
            d1 = fmaf(w1.x, v.x, fmaf(w1.y, v.y, fmaf(w1.z, v.z, fmaf(w1.w, v.w, d1))));
            d2 = fmaf(w2.x, v.x, fmaf(w2.y, v.y, fmaf(w2.z, v.z, fmaf(w2.w, v.w, d2))));
            d3 = fmaf(w3.x, v.x, fmaf(w3.y, v.y, fmaf(w3.z, v.z, fmaf(w3.w, v.w, d3))));
            d4 = fmaf(w4.x, v.x, fmaf(w4.y, v.y, fmaf(w4.z, v.z, fmaf(w4.w, v.w, d4))));
        }
        #pragma unroll
        for (int o = 16; o; o >>= 1) {
            ss += __shfl_down_sync(0xffffffffu, ss, o);
            d0 += __shfl_down_sync(0xffffffffu, d0, o);
            d1 += __shfl_down_sync(0xffffffffu, d1, o);
            d2 += __shfl_down_sync(0xffffffffu, d2, o);
            d3 += __shfl_down_sync(0xffffffffu, d3, o);
            d4 += __shfl_down_sync(0xffffffffu, d4, o);
        }
        if (ln == 0) {
            float iq = 1.0f / fmaxf(sqrtf(ss), 1e-12f);
            float* o = out + ((size_t)b * NQ + q) * NW;
            o[0] = d0 * iq; o[1] = d1 * iq; o[2] = d2 * iq; o[3] = d3 * iq; o[4] = d4 * iq;
        }
    }
}

extern "C" void kernel_launch(void* const* d_in, const int* in_sizes, int n_in,
                              void* d_out, int out_size) {
    const float* ftest  = (const float*)d_in[0];
    const float* ftrain = (const float*)d_in[1];
    const int* usp = (n_in > 4) ? (const int*)d_in[4] : nullptr;
    int B = in_sizes[1] / (NS * DIM);
    if (B > MAXB) B = MAXB;
    if (B < 1) B = 1;
    k_prep<<<2 * B, 256>>>(ftrain, usp);
    k_qp<<<B, TQP>>>();
    k_out<<<3 * B, 256>>>(ftest, usp, (float*)d_out);
}

// round 9
// speedup vs baseline: 2.0178x; 2.0178x over previous
#include <cuda_runtime.h>
#include <cuda_bf16.h>
#include <math.h>

#define NS   25      // n_shot * n_way (support samples)
#define NW   5       // n_way
#define NV   125     // QP variables
#define DIM  640
#define NQ   75
#define MAXB 512
#define TQP  160     // 5 warps for k_qp
#define HD   320     // dim chunk for k_prep

// ------------------- global scratch (static, no allocations) -------------------
__device__ float g_ftu[(size_t)MAXB * NS * DIM];     // transformed (unnormalized) train feats
__device__ float g_Kp[(size_t)2 * MAXB * NS * NS];   // partial raw Gram (per dim-chunk)
__device__ float g_W[(size_t)MAXB * NW * DIM];       // SVM weights per batch

// ------------------- simple_transform -------------------
__device__ __forceinline__ float simp_g(float u) {
    float t = __logf(__fdividef(1.0f, u + 1e-5f) + 1.0f);
    return __powf(t, -1.3f);
}
__device__ __forceinline__ float simp(float x, float c0) {
    float g = simp_g(fabsf(x));
    return (x >= 0.0f) ? (g - c0) : (c0 - g);
}

// =====================================================================
// Kernel 1: transform train chunk, partial raw Gram via warp-per-pair f4 dots
// grid = 2*B  (blockIdx.x = b*2 + chunk)
// =====================================================================
__global__ void __launch_bounds__(256) k_prep(const float* __restrict__ ftrain,
                                              const int* __restrict__ usp) {
    __shared__ __align__(16) float tile[NS * HD];   // 32 KB
    int bb = blockIdx.x, b = bb >> 1, ch = bb & 1;
    int tid = threadIdx.x;
    int us = usp ? (usp[0] != 0) : 1;
    float c0 = simp_g(0.0f);

    const float* fb = ftrain + (size_t)b * NS * DIM + ch * HD;
    float* fo = g_ftu + (size_t)b * NS * DIM + ch * HD;

    for (int e = tid; e < NS * HD; e += 256) {
        int r = e / HD, c = e - r * HD;
        float v = fb[r * DIM + c];
        if (us) v = simp(v, c0);
        tile[e] = v;
        fo[r * DIM + c] = v;
    }
    __syncthreads();

    int wp = tid >> 5, ln = tid & 31;
    float* Kout = g_Kp + ((size_t)ch * MAXB + b) * (NS * NS);
    for (int p = wp; p < 325; p += 8) {
        // closed-form upper-tri mapping: base(r) = 25r - r(r-1)/2
        int r = (int)(25.5f - sqrtf(650.25f - 2.0f * (float)p));
        if (r < 0) r = 0;
        while (25 * (r + 1) - ((r + 1) * r) / 2 <= p) r++;
        while (25 * r - (r * (r - 1)) / 2 > p) r--;
        int c = r + (p - (25 * r - (r * (r - 1)) / 2));
        const float4* A4 = (const float4*)(tile + r * HD);
        const float4* B4 = (const float4*)(tile + c * HD);
        float4 a0 = A4[ln],      v0 = B4[ln];
        float4 a1 = A4[ln + 32], v1 = B4[ln + 32];
        float acc = a0.x * v0.x;
        acc = fmaf(a0.y, v0.y, acc); acc = fmaf(a0.z, v0.z, acc); acc = fmaf(a0.w, v0.w, acc);
        acc = fmaf(a1.x, v1.x, acc); acc = fmaf(a1.y, v1.y, acc);
        acc = fmaf(a1.z, v1.z, acc); acc = fmaf(a1.w, v1.w, acc);
        if (ln < 16) {
            float4 a2 = A4[ln + 64], v2 = B4[ln + 64];
            acc = fmaf(a2.x, v2.x, acc); acc = fmaf(a2.y, v2.y, acc);
            acc = fmaf(a2.z, v2.z, acc); acc = fmaf(a2.w, v2.w, acc);
        }
        #pragma unroll
        for (int o = 16; o; o >>= 1) acc += __shfl_down_sync(0xffffffffu, acc, o);
        if (ln == 0) {
            Kout[r * NS + c] = acc;
            if (c != r) Kout[c * NS + r] = acc;
        }
    }
}

// =====================================================================
// Kernel 2: QP via IPM — one CTA (5 warps) per batch element, + W epilogue
// =====================================================================
struct QPShared {
    float M[625];
    float Hinv[NW][625];
    float Smat[625];
    float Sinv[625];
    float x[NV], s_[NV], z_[NV], bestx[NV], d_[NV];
    float rx[NV], rz[NV], r1[NV], uv[NV], rsc[NV];
    float dxa[NV], dsa[NV], dza[NV];
    float dxc[NV], dsc[NV], dzc[NV];
    float y_[NS], ry[NS], gvec[NS], dya[NS], dyc[NS];
    float inv[NS];
    float red[8];
};

__device__ __forceinline__ float blk_sum5(float v, volatile float* red) {
    int tid = threadIdx.x;
    __syncthreads();
    #pragma unroll
    for (int o = 16; o; o >>= 1) v += __shfl_down_sync(0xffffffffu, v, o);
    if ((tid & 31) == 0) red[tid >> 5] = v;
    __syncthreads();
    return red[0] + red[1] + red[2] + red[3] + red[4];
}
__device__ __forceinline__ float blk_min5(float v, volatile float* red) {
    int tid = threadIdx.x;
    __syncthreads();
    #pragma unroll
    for (int o = 16; o; o >>= 1) v = fminf(v, __shfl_down_sync(0xffffffffu, v, o));
    if ((tid & 31) == 0) red[tid >> 5] = v;
    __syncthreads();
    return fminf(fminf(fminf(red[0], red[1]), fminf(red[2], red[3])), red[4]);
}

// In-place Gauss-Jordan inverse of a 25x25 matrix held row-per-lane in registers.
// Fully warp-uniform control flow (no divergent trip counts, no syncwarp, no LDS).
// Lanes 25-31 carry garbage and never write.  SPD input -> no pivoting needed.
__device__ __forceinline__ void gj25(float* a, int ln) {
    bool act = (ln < NS);
    #pragma unroll
    for (int j = 0; j < NS; j++) {
        float f = a[j];                                   // A[i][j]
        float piv = __shfl_sync(0xffffffffu, f, j);       // A[j][j]
        float ip = 1.0f / piv;
        bool isj = (ln == j);
        #pragma unroll
        for (int k = 0; k < NS; k++) {
            if (k == j) continue;
            float r = __shfl_sync(0xffffffffu, a[k], j) * ip;  // scaled pivot row
            float upd = fmaf(-f, r, a[k]);
            a[k] = isj ? r : upd;
        }
        float cj = -f * ip;
        a[j] = isj ? ip : cj;
        (void)act;
    }
}

// Factorize: Hinv_w = (M + diag(d_w))^{-1} per warp; Sinv = (sum_w Hinv_w)^{-1}.
// Single gj25 instance via phase loop (I-cache friendly).
__device__ void factorize(QPShared& S) {
    int tid = threadIdx.x, wp = tid >> 5, ln = tid & 31;
    float a[NS];
    #pragma unroll 1
    for (int ph = 0; ph < 2; ph++) {
        if (ph == 0) {
            if (ln < NS) {
                #pragma unroll
                for (int k = 0; k < NS; k++) a[k] = S.M[ln * NS + k];
                #pragma unroll
                for (int k = 0; k < NS; k++) if (k == ln) a[k] += S.d_[ln * NW + wp];
            }
        } else {
            for (int e = tid; e < 625; e += TQP)
                S.Smat[e] = S.Hinv[0][e] + S.Hinv[1][e] + S.Hinv[2][e]
                          + S.Hinv[3][e] + S.Hinv[4][e];
            __syncthreads();
            if (ln < NS) {
                #pragma unroll
                for (int k = 0; k < NS; k++) a[k] = S.Smat[ln * NS + k];
            }
        }
        gj25(a, ln);
        if (ph == 0) {
            if (ln < NS) {
                #pragma unroll
                for (int k = 0; k < NS; k++) S.Hinv[wp][ln * NS + k] = a[k];
            }
        } else {
            if (wp == 0 && ln < NS) {
                #pragma unroll
                for (int k = 0; k < NS; k++) S.Sinv[ln * NS + k] = a[k];
            }
        }
        __syncthreads();
    }
}

// KKT apply: NULL pointer == zero vector
__device__ void applyKKT(QPShared& S, const float* rx, const float* rs,
                         const float* rz, const float* ry,
                         float* dx, float* ds, float* dz, float* dy) {
    int tid = threadIdx.x, wp = tid >> 5, ln = tid & 31;
    if (tid < NV) {
        float rxv = rx ? rx[tid] : 0.0f;
        float rsv = rs ? rs[tid] : 0.0f;
        float rzv = rz ? rz[tid] : 0.0f;
        S.r1[tid] = -rxv - S.d_[tid] * rzv + rsv;
    }
    __syncthreads();
    if (ln < NS) {                      // u_w = H_w^{-1} r1_w
        const float* Hi = S.Hinv[wp] + ln * NS;
        float acc = 0.0f;
        #pragma unroll
        for (int j = 0; j < NS; j++) acc = fmaf(Hi[j], S.r1[j * NW + wp], acc);
        S.uv[ln * NW + wp] = acc;
    }
    __syncthreads();
    if (tid < NS) {
        float g = S.uv[tid * NW] + S.uv[tid * NW + 1] + S.uv[tid * NW + 2]
                + S.uv[tid * NW + 3] + S.uv[tid * NW + 4];
        if (ry) g += ry[tid];
        S.gvec[tid] = g;
    }
    __syncthreads();
    if (wp == 0 && ln < NS) {           // dy = S_y^{-1} g
        const float* Si = S.Sinv + ln * NS;
        float acc = 0.0f;
        #pragma unroll
        for (int j = 0; j < NS; j++) acc = fmaf(Si[j], S.gvec[j], acc);
        dy[ln] = acc;
    }
    __syncthreads();
    if (ln < NS) {                      // dx = u - H^{-1} A^T dy
        const float* Hi = S.Hinv[wp] + ln * NS;
        float acc = 0.0f;
        #pragma unroll
        for (int j = 0; j < NS; j++) acc = fmaf(Hi[j], dy[j], acc);
        dx[ln * NW + wp] = S.uv[ln * NW + wp] - acc;
    }
    __syncthreads();
    if (tid < NV) {
        float rsv = rs ? rs[tid] : 0.0f;
        float rzv = rz ? rz[tid] : 0.0f;
        float dxv = dx[tid];
        dz[tid] = S.d_[tid] * (dxv + rzv) - rsv;
        ds[tid] = -dxv - rzv;
    }
    __syncthreads();
}

__global__ void __launch_bounds__(TQP) k_qp() {
    __shared__ QPShared S;
    int b = blockIdx.x, tid = threadIdx.x;
    // sum partial raw Gram
    for (int e = tid; e < 625; e += TQP)
        S.M[e] = g_Kp[(size_t)b * 625 + e] + g_Kp[((size_t)MAXB + b) * 625 + e];
    __syncthreads();
    if (tid < NS)
        S.inv[tid] = 1.0f / fmaxf(sqrtf(S.M[tid * NS + tid]), 1e-12f);
    __syncthreads();
    for (int e = tid; e < 625; e += TQP) {
        int r = e / NS, c = e - r * NS;
        S.M[e] = S.M[e] * S.inv[r] * S.inv[c] + ((r == c) ? 1.0f : 0.0f);
    }
    if (tid < NV) {
        S.d_[tid] = 1.0f;
        int sidx = tid / NW, w = tid - sidx * NW;
        float oh = ((sidx % NW) == w) ? 1.0f : 0.0f;
        S.rx[tid] = -oh;          // p
        S.rz[tid] = -0.1f * oh;   // -h
    }
    __syncthreads();
    factorize(S);
    applyKKT(S, S.rx, nullptr, S.rz, nullptr, S.x, S.s_, S.z_, S.y_);
    // shift s, z
    float mv = (tid < NV) ? S.s_[tid] : 3.0e38f;
    float m = blk_min5(mv, S.red);
    if (tid < NV && m < 0.0f) S.s_[tid] -= (m - 1.0f);
    mv = (tid < NV) ? S.z_[tid] : 3.0e38f;
    m = blk_min5(mv, S.red);
    if (tid < NV && m < 0.0f) S.z_[tid] -= (m - 1.0f);
    __syncthreads();

    float best_res = 3.0e38f;
    int wp = tid >> 5, ln = tid & 31;
    for (int it = 0; it < 3; it++) {
        if (ln < NS) {
            const float* Mr = S.M + ln * NS;
            float qx = 0.0f;
            #pragma unroll
            for (int j = 0; j < NS; j++) qx = fmaf(Mr[j], S.x[j * NW + wp], qx);
            int v = ln * NW + wp;
            float oh = ((ln % NW) == wp) ? 1.0f : 0.0f;
            S.rx[v] = S.y_[ln] + S.z_[v] + qx - oh;
            S.rz[v] = S.x[v] + S.s_[v] - 0.1f * oh;
        }
        if (tid < NS)
            S.ry[tid] = S.x[tid * NW] + S.x[tid * NW + 1] + S.x[tid * NW + 2]
                      + S.x[tid * NW + 3] + S.x[tid * NW + 4];
        float szv = (tid < NV) ? S.s_[tid] * S.z_[tid] : 0.0f;
        float sz = blk_sum5(szv, S.red);
        float mu = fabsf(sz) * (1.0f / 125.0f);
        float t2 = (tid < NV) ? S.rx[tid] * S.rx[tid] : 0.0f;
        float nrx = sqrtf(blk_sum5(t2, S.red) + 1e-30f);
        t2 = (tid < NV) ? S.rz[tid] * S.rz[tid] : 0.0f;
        float nrz = sqrtf(blk_sum5(t2, S.red) + 1e-30f);
        t2 = (tid < NS) ? S.ry[tid] * S.ry[tid] : 0.0f;
        float nry = sqrtf(blk_sum5(t2, S.red) + 1e-30f);
        float res = nrz + nry + nrx + 125.0f * mu;
        if (res < best_res) { best_res = res; if (tid < NV) S.bestx[tid] = S.x[tid]; }
        if (it == 2) break;

        if (tid < NV) S.d_[tid] = S.z_[tid] / S.s_[tid];
        __syncthreads();
        factorize(S);
        applyKKT(S, S.rx, S.z_, S.rz, S.ry, S.dxa, S.dsa, S.dza, S.dya);
        float az = (tid < NV) ? ((S.dza[tid] < 0.0f) ? -S.z_[tid] / S.dza[tid] : 1e12f) : 1e12f;
        float as = (tid < NV) ? ((S.dsa[tid] < 0.0f) ? -S.s_[tid] / S.dsa[tid] : 1e12f) : 1e12f;
        float alpha = fminf(blk_min5(fminf(az, as), S.red), 1.0f);
        float tt = (tid < NV) ? (S.s_[tid] + alpha * S.dsa[tid]) * (S.z_[tid] + alpha * S.dza[tid]) : 0.0f;
        float sumt = blk_sum5(tt, S.red);
        float ratio = sumt / sz;
        float musig = mu * ratio * ratio * ratio;
        if (tid < NV) S.rsc[tid] = (-musig + S.dsa[tid] * S.dza[tid]) / S.s_[tid];
        __syncthreads();
        applyKKT(S, nullptr, S.rsc, nullptr, nullptr, S.dxc, S.dsc, S.dzc, S.dyc);
        if (tid < NV) { S.dxa[tid] += S.dxc[tid]; S.dsa[tid] += S.dsc[tid]; S.dza[tid] += S.dzc[tid]; }
        if (tid < NS) S.dya[tid] += S.dyc[tid];
        __syncthreads();
        az = (tid < NV) ? ((S.dza[tid] < 0.0f) ? -S.z_[tid] / S.dza[tid] : 1e12f) : 1e12f;
        as = (tid < NV) ? ((S.dsa[tid] < 0.0f) ? -S.s_[tid] / S.dsa[tid] : 1e12f) : 1e12f;
        alpha = fminf(0.999f * blk_min5(fminf(az, as), S.red), 1.0f);
        if (tid < NV) {
            S.x[tid]  += alpha * S.dxa[tid];
            S.s_[tid] += alpha * S.dsa[tid];
            S.z_[tid] += alpha * S.dza[tid];
        }
        if (tid < NS) S.y_[tid] += alpha * S.dya[tid];
        __syncthreads();
    }
    // ---- epilogue: W = (bestx * invn)^T ftu  (5 x 640) ----
    if (tid < NV) S.x[tid] = S.bestx[tid] * S.inv[tid / NW];
    __syncthreads();
    const float* fu = g_ftu + (size_t)b * NS * DIM;
    float* Wo = g_W + (size_t)b * (NW * DIM);
    for (int dd = tid; dd < DIM; dd += TQP) {
        float a0 = 0, a1 = 0, a2 = 0, a3 = 0, a4 = 0;
        #pragma unroll
        for (int s = 0; s < NS; s++) {
            float fv = fu[s * DIM + dd];
            a0 = fmaf(S.x[s * NW + 0], fv, a0);
            a1 = fmaf(S.x[s * NW + 1], fv, a1);
            a2 = fmaf(S.x[s * NW + 2], fv, a2);
            a3 = fmaf(S.x[s * NW + 3], fv, a3);
            a4 = fmaf(S.x[s * NW + 4], fv, a4);
        }
        Wo[0 * DIM + dd] = a0; Wo[1 * DIM + dd] = a1; Wo[2 * DIM + dd] = a2;
        Wo[3 * DIM + dd] = a3; Wo[4 * DIM + dd] = a4;
    }
}

// =====================================================================
// Kernel 3: out[q,w] = <W_w, t(fq_q)> / ||t(fq_q)||, float4 path
// grid = 5*B, 15 queries per CTA
// =====================================================================
__global__ void __launch_bounds__(256) k_out(const float* __restrict__ ftest,
                                             const int* __restrict__ usp,
                                             float* __restrict__ out) {
    __shared__ __align__(16) float W[NW * DIM];
    int bb = blockIdx.x, b = bb / 5, part = bb - b * 5;
    int tid = threadIdx.x;
    int us = usp ? (usp[0] != 0) : 1;
    float c0 = simp_g(0.0f);
    for (int e = tid; e < NW * DIM; e += 256) W[e] = g_W[(size_t)b * NW * DIM + e];
    __syncthreads();
    int wp = tid >> 5, ln = tid & 31;
    const float* fq = ftest + (size_t)b * NQ * DIM;
    int q0 = part * 15;
    for (int q = q0 + wp; q < q0 + 15; q += 8) {
        const float4* row4 = (const float4*)(fq + (size_t)q * DIM);
        float ss = 0, d0 = 0, d1 = 0, d2 = 0, d3 = 0, d4 = 0;
        #pragma unroll
        for (int j = 0; j < 5; j++) {
            int i4 = ln + 32 * j;
            float4 v = row4[i4];
            if (us) {
                v.x = simp(v.x, c0); v.y = simp(v.y, c0);
                v.z = simp(v.z, c0); v.w = simp(v.w, c0);
            }
            ss = fmaf(v.x, v.x, fmaf(v.y, v.y, fmaf(v.z, v.z, fmaf(v.w, v.w, ss))));
            float4 w0 = ((const float4*)(W + 0 * DIM))[i4];
            float4 w1 = ((const float4*)(W + 1 * DIM))[i4];
            float4 w2 = ((const float4*)(W + 2 * DIM))[i4];
            float4 w3 = ((const float4*)(W + 3 * DIM))[i4];
            float4 w4 = ((const float4*)(W + 4 * DIM))[i4];
            d0 = fmaf(w0.x, v.x, fmaf(w0.y, v.y, fmaf(w0.z, v.z, fmaf(w0.w, v.w, d0))));
            d1 = fmaf(w1.x, v.x, fmaf(w1.y, v.y, fmaf(w1.z, v.z, fmaf(w1.w, v.w, d1))));
            d2 = fmaf(w2.x, v.x, fmaf(w2.y, v.y, fmaf(w2.z, v.z, fmaf(w2.w, v.w, d2))));
            d3 = fmaf(w3.x, v.x, fmaf(w3.y, v.y, fmaf(w3.z, v.z, fmaf(w3.w, v.w, d3))));
            d4 = fmaf(w4.x, v.x, fmaf(w4.y, v.y, fmaf(w4.z, v.z, fmaf(w4.w, v.w, d4))));
        }
        #pragma unroll
        for (int o = 16; o; o >>= 1) {
            ss += __shfl_down_sync(0xffffffffu, ss, o);
            d0 += __shfl_down_sync(0xffffffffu, d0, o);
            d1 += __shfl_down_sync(0xffffffffu, d1, o);
            d2 += __shfl_down_sync(0xffffffffu, d2, o);
            d3 += __shfl_down_sync(0xffffffffu, d3, o);
            d4 += __shfl_down_sync(0xffffffffu, d4, o);
        }
        if (ln == 0) {
            float iq = 1.0f / fmaxf(sqrtf(ss), 1e-12f);
            float* o = out + ((size_t)b * NQ + q) * NW;
            o[0] = d0 * iq; o[1] = d1 * iq; o[2] = d2 * iq; o[3] = d3 * iq; o[4] = d4 * iq;
        }
    }
}

extern "C" void kernel_launch(void* const* d_in, const int* in_sizes, int n_in,
                              void* d_out, int out_size) {
    const float* ftest  = (const float*)d_in[0];
    const float* ftrain = (const float*)d_in[1];
    const int* usp = (n_in > 4) ? (const int*)d_in[4] : nullptr;
    int B = in_sizes[1] / (NS * DIM);
    if (B > MAXB) B = MAXB;
    if (B < 1) B = 1;
    k_prep<<<2 * B, 256>>>(ftrain, usp);
    k_qp<<<B, TQP>>>();
    k_out<<<5 * B, 256>>>(ftest, usp, (float*)d_out);
}

// round 12
// speedup vs baseline: 2.4206x; 1.1996x over previous
#include <cuda_runtime.h>
#include <cuda_bf16.h>
#include <math.h>

#define NS   25      // n_shot * n_way (support samples)
#define NW   5       // n_way
#define NV   125     // QP variables
#define DIM  640
#define NQ   75
#define MAXB 512
#define TQP  160     // 5 warps for k_qp
#define HD   320     // dim chunk for k_prep

// ------------------- global scratch (static, no allocations) -------------------
__device__ float g_ftu[(size_t)MAXB * NS * DIM];     // transformed (unnormalized) train feats
__device__ float g_Kp[(size_t)2 * MAXB * NS * NS];   // partial raw Gram (per dim-chunk)
__device__ float g_W[(size_t)MAXB * NW * DIM];       // SVM weights per batch

// ------------------- simple_transform -------------------
__device__ __forceinline__ float simp_g(float u) {
    float t = __logf(__fdividef(1.0f, u + 1e-5f) + 1.0f);
    return __powf(t, -1.3f);
}
__device__ __forceinline__ float simp(float x, float c0) {
    float g = simp_g(fabsf(x));
    return (x >= 0.0f) ? (g - c0) : (c0 - g);
}

// =====================================================================
// Kernel 1: transform train chunk, partial raw Gram via warp-per-pair f4 dots
// grid = 2*B  (blockIdx.x = b*2 + chunk)
// =====================================================================
__global__ void __launch_bounds__(256) k_prep(const float* __restrict__ ftrain,
                                              const int* __restrict__ usp) {
    __shared__ __align__(16) float tile[NS * HD];   // 32 KB
    __shared__ uchar2 prs[325];
    int bb = blockIdx.x, b = bb >> 1, ch = bb & 1;
    int tid = threadIdx.x;
    int us = usp ? (usp[0] != 0) : 1;
    float c0 = simp_g(0.0f);

    // build (r,c) pair table once
    for (int p = tid; p < 325; p += 256) {
        int r = 0, rem = p;
        while (rem >= NS - r) { rem -= NS - r; r++; }
        prs[p] = make_uchar2((unsigned char)r, (unsigned char)(r + rem));
    }

    const float* fb = ftrain + (size_t)b * NS * DIM + ch * HD;
    float* fo = g_ftu + (size_t)b * NS * DIM + ch * HD;

    for (int e = tid; e < NS * HD; e += 256) {
        int r = e / HD, c = e - r * HD;
        float v = fb[r * DIM + c];
        if (us) v = simp(v, c0);
        tile[e] = v;
        fo[r * DIM + c] = v;
    }
    __syncthreads();

    int wp = tid >> 5, ln = tid & 31;
    float* Kout = g_Kp + ((size_t)ch * MAXB + b) * (NS * NS);
    for (int p = wp; p < 325; p += 8) {
        uchar2 pc = prs[p];
        int r = pc.x, c = pc.y;
        const float4* A4 = (const float4*)(tile + r * HD);
        const float4* B4 = (const float4*)(tile + c * HD);
        float4 a0 = A4[ln],      v0 = B4[ln];
        float4 a1 = A4[ln + 32], v1 = B4[ln + 32];
        float acc = a0.x * v0.x;
        acc = fmaf(a0.y, v0.y, acc); acc = fmaf(a0.z, v0.z, acc); acc = fmaf(a0.w, v0.w, acc);
        acc = fmaf(a1.x, v1.x, acc); acc = fmaf(a1.y, v1.y, acc);
        acc = fmaf(a1.z, v1.z, acc); acc = fmaf(a1.w, v1.w, acc);
        if (ln < 16) {
            float4 a2 = A4[ln + 64], v2 = B4[ln + 64];
            acc = fmaf(a2.x, v2.x, acc); acc = fmaf(a2.y, v2.y, acc);
            acc = fmaf(a2.z, v2.z, acc); acc = fmaf(a2.w, v2.w, acc);
        }
        #pragma unroll
        for (int o = 16; o; o >>= 1) acc += __shfl_down_sync(0xffffffffu, acc, o);
        if (ln == 0) {
            Kout[r * NS + c] = acc;
            if (c != r) Kout[c * NS + r] = acc;
        }
    }
}

// =====================================================================
// Kernel 2: QP via IPM — one CTA (5 warps) per batch element, + W epilogue
// =====================================================================
struct QPShared {
    float M[625];
    float Hinv[NW][625];
    float Smat[625];
    float Sinv[625];
    float x[NV], s_[NV], z_[NV], bestx[NV], d_[NV];
    float rx[NV], rz[NV], r1[NV], uv[NV], rsc[NV];
    float dxa[NV], dsa[NV], dza[NV];
    float dxc[NV], dsc[NV], dzc[NV];
    float y_[NS], ry[NS], gvec[NS], dya[NS], dyc[NS];
    float inv[NS];
    float red[8];
    float red4[NW][4];
};

__device__ __forceinline__ float blk_sum5(float v, volatile float* red) {
    int tid = threadIdx.x;
    __syncthreads();
    #pragma unroll
    for (int o = 16; o; o >>= 1) v += __shfl_down_sync(0xffffffffu, v, o);
    if ((tid & 31) == 0) red[tid >> 5] = v;
    __syncthreads();
    return red[0] + red[1] + red[2] + red[3] + red[4];
}
__device__ __forceinline__ float blk_min5(float v, volatile float* red) {
    int tid = threadIdx.x;
    __syncthreads();
    #pragma unroll
    for (int o = 16; o; o >>= 1) v = fminf(v, __shfl_down_sync(0xffffffffu, v, o));
    if ((tid & 31) == 0) red[tid >> 5] = v;
    __syncthreads();
    return fminf(fminf(fminf(red[0], red[1]), fminf(red[2], red[3])), red[4]);
}

// In-place Gauss-Jordan inverse of 25x25, row-per-lane in registers.
// Warp-uniform control flow; lanes 25-31 carry garbage, never stored.
__device__ __forceinline__ void gj25(float* a, int ln) {
    #pragma unroll
    for (int j = 0; j < NS; j++) {
        float f = a[j];
        float piv = __shfl_sync(0xffffffffu, f, j);
        float ip = 1.0f / piv;
        bool isj = (ln == j);
        #pragma unroll
        for (int k = 0; k < NS; k++) {
            if (k == j) continue;
            float r = __shfl_sync(0xffffffffu, a[k], j) * ip;
            float upd = fmaf(-f, r, a[k]);
            a[k] = isj ? r : upd;
        }
        a[j] = isj ? ip : (-f * ip);
    }
}

// Hinv_w = (M + diag(d_w))^{-1} per warp; Sinv = (sum_w Hinv_w)^{-1} (warp0).
// __noinline__: exactly one gj25 body in the binary, called 3x.
__device__ __noinline__ void factorize(QPShared& S) {
    int tid = threadIdx.x, wp = tid >> 5, ln = tid & 31;
    float a[NS];
    if (ln < NS) {
        #pragma unroll
        for (int k = 0; k < NS; k++) a[k] = S.M[ln * NS + k];
        a[ln] += S.d_[ln * NW + wp];
    }
    gj25(a, ln);
    if (ln < NS) {
        #pragma unroll
        for (int k = 0; k < NS; k++) S.Hinv[wp][ln * NS + k] = a[k];
    }
    __syncthreads();
    for (int e = tid; e < 625; e += TQP)
        S.Smat[e] = S.Hinv[0][e] + S.Hinv[1][e] + S.Hinv[2][e]
                  + S.Hinv[3][e] + S.Hinv[4][e];
    __syncthreads();
    if (wp == 0) {
        if (ln < NS) {
            #pragma unroll
            for (int k = 0; k < NS; k++) a[k] = S.Smat[ln * NS + k];
        }
        gj25(a, ln);
        if (ln < NS) {
            #pragma unroll
            for (int k = 0; k < NS; k++) S.Sinv[ln * NS + k] = a[k];
        }
    }
    __syncthreads();
}

// KKT apply: NULL pointer == zero vector.  5 internal barriers.
__device__ __noinline__ void applyKKT(QPShared& S, const float* rx, const float* rs,
                                      const float* rz, const float* ry,
                                      float* dx, float* ds, float* dz, float* dy) {
    int tid = threadIdx.x, wp = tid >> 5, ln = tid & 31;
    if (tid < NV) {
        float rxv = rx ? rx[tid] : 0.0f;
        float rsv = rs ? rs[tid] : 0.0f;
        float rzv = rz ? rz[tid] : 0.0f;
        S.r1[tid] = -rxv - S.d_[tid] * rzv + rsv;
    }
    __syncthreads();
    if (ln < NS) {                      // u_w = H_w^{-1} r1_w
        const float* Hi = S.Hinv[wp] + ln * NS;
        float acc = 0.0f;
        #pragma unroll
        for (int j = 0; j < NS; j++) acc = fmaf(Hi[j], S.r1[j * NW + wp], acc);
        S.uv[ln * NW + wp] = acc;
    }
    __syncthreads();
    if (tid < NS) {
        float g = S.uv[tid * NW] + S.uv[tid * NW + 1] + S.uv[tid * NW + 2]
                + S.uv[tid * NW + 3] + S.uv[tid * NW + 4];
        if (ry) g += ry[tid];
        S.gvec[tid] = g;
    }
    __syncthreads();
    if (wp == 0 && ln < NS) {           // dy = S_y^{-1} g
        const float* Si = S.Sinv + ln * NS;
        float acc = 0.0f;
        #pragma unroll
        for (int j = 0; j < NS; j++) acc = fmaf(Si[j], S.gvec[j], acc);
        dy[ln] = acc;
    }
    __syncthreads();
    if (ln < NS) {                      // dx = u - H^{-1} A^T dy
        const float* Hi = S.Hinv[wp] + ln * NS;
        float acc = 0.0f;
        #pragma unroll
        for (int j = 0; j < NS; j++) acc = fmaf(Hi[j], dy[j], acc);
        dx[ln * NW + wp] = S.uv[ln * NW + wp] - acc;
    }
    __syncthreads();
    if (tid < NV) {                     // own-thread writes; no trailing barrier
        float rsv = rs ? rs[tid] : 0.0f;
        float rzv = rz ? rz[tid] : 0.0f;
        float dxv = dx[tid];
        dz[tid] = S.d_[tid] * (dxv + rzv) - rsv;
        ds[tid] = -dxv - rzv;
    }
}

__global__ void __launch_bounds__(TQP) k_qp() {
    __shared__ QPShared S;
    int b = blockIdx.x, tid = threadIdx.x;
    int wp = tid >> 5, ln = tid & 31;
    for (int e = tid; e < 625; e += TQP)
        S.M[e] = g_Kp[(size_t)b * 625 + e] + g_Kp[((size_t)MAXB + b) * 625 + e];
    __syncthreads();
    if (tid < NS)
        S.inv[tid] = 1.0f / fmaxf(sqrtf(S.M[tid * NS + tid]), 1e-12f);
    __syncthreads();
    for (int e = tid; e < 625; e += TQP) {
        int r = e / NS, c = e - r * NS;
        S.M[e] = S.M[e] * S.inv[r] * S.inv[c] + ((r == c) ? 1.0f : 0.0f);
    }
    if (tid < NV) {
        S.d_[tid] = 1.0f;
        int sidx = tid / NW, w = tid - sidx * NW;
        float oh = ((sidx % NW) == w) ? 1.0f : 0.0f;
        S.rx[tid] = -oh;          // p
        S.rz[tid] = -0.1f * oh;   // -h
    }
    __syncthreads();
    factorize(S);
    applyKKT(S, S.rx, nullptr, S.rz, nullptr, S.x, S.s_, S.z_, S.y_);
    // shift s, z  (blk_min5 leading barrier covers the applyKKT tail writes)
    float mv = (tid < NV) ? S.s_[tid] : 3.0e38f;
    float m = blk_min5(mv, S.red);
    if (tid < NV && m < 0.0f) S.s_[tid] -= (m - 1.0f);
    mv = (tid < NV) ? S.z_[tid] : 3.0e38f;
    m = blk_min5(mv, S.red);
    if (tid < NV && m < 0.0f) S.z_[tid] -= (m - 1.0f);
    __syncthreads();

    float best_res = 3.0e38f;
    for (int it = 0; it < 3; it++) {
        if (ln < NS) {
            const float* Mr = S.M + ln * NS;
            float qx = 0.0f;
            #pragma unroll
            for (int j = 0; j < NS; j++) qx = fmaf(Mr[j], S.x[j * NW + wp], qx);
            int v = ln * NW + wp;
            float oh = ((ln % NW) == wp) ? 1.0f : 0.0f;
            S.rx[v] = S.y_[ln] + S.z_[v] + qx - oh;
            S.rz[v] = S.x[v] + S.s_[v] - 0.1f * oh;
        }
        if (tid < NS)
            S.ry[tid] = S.x[tid * NW] + S.x[tid * NW + 1] + S.x[tid * NW + 2]
                      + S.x[tid * NW + 3] + S.x[tid * NW + 4];
        __syncthreads();
        // fused 4-way reduction: sz, |rx|^2, |rz|^2, |ry|^2  (2 barriers)
        float v0 = (tid < NV) ? S.s_[tid] * S.z_[tid] : 0.0f;
        float v1 = (tid < NV) ? S.rx[tid] * S.rx[tid] : 0.0f;
        float v2 = (tid < NV) ? S.rz[tid] * S.rz[tid] : 0.0f;
        float v3 = (tid < NS) ? S.ry[tid] * S.ry[tid] : 0.0f;
        #pragma unroll
        for (int o = 16; o; o >>= 1) {
            v0 += __shfl_down_sync(0xffffffffu, v0, o);
            v1 += __shfl_down_sync(0xffffffffu, v1, o);
            v2 += __shfl_down_sync(0xffffffffu, v2, o);
            v3 += __shfl_down_sync(0xffffffffu, v3, o);
        }
        if (ln == 0) {
            S.red4[wp][0] = v0; S.red4[wp][1] = v1;
            S.red4[wp][2] = v2; S.red4[wp][3] = v3;
        }
        __syncthreads();
        float sz  = S.red4[0][0] + S.red4[1][0] + S.red4[2][0] + S.red4[3][0] + S.red4[4][0];
        float nrx = sqrtf(S.red4[0][1] + S.red4[1][1] + S.red4[2][1] + S.red4[3][1] + S.red4[4][1] + 1e-30f);
        float nrz = sqrtf(S.red4[0][2] + S.red4[1][2] + S.red4[2][2] + S.red4[3][2] + S.red4[4][2] + 1e-30f);
        float nry = sqrtf(S.red4[0][3] + S.red4[1][3] + S.red4[2][3] + S.red4[3][3] + S.red4[4][3] + 1e-30f);
        float mu = fabsf(sz) * (1.0f / 125.0f);
        float res = nrz + nry + nrx + 125.0f * mu;
        if (res < best_res) { best_res = res; if (tid < NV) S.bestx[tid] = S.x[tid]; }
        if (it == 2) break;

        if (tid < NV) S.d_[tid] = S.z_[tid] / S.s_[tid];
        __syncthreads();
        factorize(S);
        applyKKT(S, S.rx, S.z_, S.rz, S.ry, S.dxa, S.dsa, S.dza, S.dya);
        float az = (tid < NV) ? ((S.dza[tid] < 0.0f) ? -S.z_[tid] / S.dza[tid] : 1e12f) : 1e12f;
        float as = (tid < NV) ? ((S.dsa[tid] < 0.0f) ? -S.s_[tid] / S.dsa[tid] : 1e12f) : 1e12f;
        float alpha = fminf(blk_min5(fminf(az, as), S.red), 1.0f);
        float tt = (tid < NV) ? (S.s_[tid] + alpha * S.dsa[tid]) * (S.z_[tid] + alpha * S.dza[tid]) : 0.0f;
        float sumt = blk_sum5(tt, S.red);
        float ratio = sumt / sz;
        float musig = mu * ratio * ratio * ratio;
        if (tid < NV) S.rsc[tid] = (-musig + S.dsa[tid] * S.dza[tid]) / S.s_[tid];
        __syncthreads();
        applyKKT(S, nullptr, S.rsc, nullptr, nullptr, S.dxc, S.dsc, S.dzc, S.dyc);
        __syncthreads();   // dyc written by warp0; dya update below crosses warps only for dy
        if (tid < NV) { S.dxa[tid] += S.dxc[tid]; S.dsa[tid] += S.dsc[tid]; S.dza[tid] += S.dzc[tid]; }
        if (tid < NS) S.dya[tid] += S.dyc[tid];
        az = (tid < NV) ? ((S.dza[tid] < 0.0f) ? -S.z_[tid] / S.dza[tid] : 1e12f) : 1e12f;
        as = (tid < NV) ? ((S.dsa[tid] < 0.0f) ? -S.s_[tid] / S.dsa[tid] : 1e12f) : 1e12f;
        alpha = fminf(0.999f * blk_min5(fminf(az, as), S.red), 1.0f);
        if (tid < NV) {
            S.x[tid]  += alpha * S.dxa[tid];
            S.s_[tid] += alpha * S.dsa[tid];
            S.z_[tid] += alpha * S.dza[tid];
        }
        if (tid < NS) S.y_[tid] += alpha * S.dya[tid];
        __syncthreads();
    }
    // ---- epilogue: W = (bestx * invn)^T ftu  (5 x 640) ----
    if (tid < NV) S.x[tid] = S.bestx[tid] * S.inv[tid / NW];
    __syncthreads();
    const float* fu = g_ftu + (size_t)b * NS * DIM;
    float* Wo = g_W + (size_t)b * (NW * DIM);
    for (int dd = tid; dd < DIM; dd += TQP) {
        float a0 = 0, a1 = 0, a2 = 0, a3 = 0, a4 = 0;
        #pragma unroll
        for (int s = 0; s < NS; s++) {
            float fv = fu[s * DIM + dd];
            a0 = fmaf(S.x[s * NW + 0], fv, a0);
            a1 = fmaf(S.x[s * NW + 1], fv, a1);
            a2 = fmaf(S.x[s * NW + 2], fv, a2);
            a3 = fmaf(S.x[s * NW + 3], fv, a3);
            a4 = fmaf(S.x[s * NW + 4], fv, a4);
        }
        Wo[0 * DIM + dd] = a0; Wo[1 * DIM + dd] = a1; Wo[2 * DIM + dd] = a2;
        Wo[3 * DIM + dd] = a3; Wo[4 * DIM + dd] = a4;
    }
}

// =====================================================================
// Kernel 3: out[q,w] = <W_w, t(fq_q)> / ||t(fq_q)||, float4 path
// grid = 5*B, 160 threads, 3 queries per warp (balanced)
// =====================================================================
__global__ void __launch_bounds__(160) k_out(const float* __restrict__ ftest,
                                             const int* __restrict__ usp,
                                             float* __restrict__ out) {
    __shared__ __align__(16) float W[NW * DIM];
    int bb = blockIdx.x, b = bb / 5, part = bb - b * 5;
    int tid = threadIdx.x;
    int us = usp ? (usp[0] != 0) : 1;
    float c0 = simp_g(0.0f);
    {
        const float4* src = (const float4*)(g_W + (size_t)b * NW * DIM);
        float4* dst = (float4*)W;
        for (int e = tid; e < NW * DIM / 4; e += 160) dst[e] = src[e];
    }
    __syncthreads();
    int wp = tid >> 5, ln = tid & 31;
    const float* fq = ftest + (size_t)b * NQ * DIM;
    int q0 = part * 15 + wp * 3;
    #pragma unroll 1
    for (int qq = 0; qq < 3; qq++) {
        int q = q0 + qq;
        const float4* row4 = (const float4*)(fq + (size_t)q * DIM);
        float ss = 0, d0 = 0, d1 = 0, d2 = 0, d3 = 0, d4 = 0;
        #pragma unroll
        for (int j = 0; j < 5; j++) {
            int i4 = ln + 32 * j;
            float4 v = row4[i4];
            if (us) {
                v.x = simp(v.x, c0); v.y = simp(v.y, c0);
                v.z = simp(v.z, c0); v.w = simp(v.w, c0);
            }
            ss = fmaf(v.x, v.x, fmaf(v.y, v.y, fmaf(v.z, v.z, fmaf(v.w, v.w, ss))));
            float4 w0 = ((const float4*)(W + 0 * DIM))[i4];
            float4 w1 = ((const float4*)(W + 1 * DIM))[i4];
            float4 w2 = ((const float4*)(W + 2 * DIM))[i4];
            float4 w3 = ((const float4*)(W + 3 * DIM))[i4];
            float4 w4 = ((const float4*)(W + 4 * DIM))[i4];
            d0 = fmaf(w0.x, v.x, fmaf(w0.y, v.y, fmaf(w0.z, v.z, fmaf(w0.w, v.w, d0))));
            d1 = fmaf(w1.x, v.x, fmaf(w1.y, v.y, fmaf(w1.z, v.z, fmaf(w1.w, v.w, d1))));
            d2 = fmaf(w2.x, v.x, fmaf(w2.y, v.y, fmaf(w2.z, v.z, fmaf(w2.w, v.w, d2))));
            d3 = fmaf(w3.x, v.x, fmaf(w3.y, v.y, fmaf(w3.z, v.z, fmaf(w3.w, v.w, d3))));
            d4 = fmaf(w4.x, v.x, fmaf(w4.y, v.y, fmaf(w4.z, v.z, fmaf(w4.w, v.w, d4))));
        }
        #pragma unroll
        for (int o = 16; o; o >>= 1) {
            ss += __shfl_down_sync(0xffffffffu, ss, o);
            d0 += __shfl_down_sync(0xffffffffu, d0, o);
            d1 += __shfl_down_sync(0xffffffffu, d1, o);
            d2 += __shfl_down_sync(0xffffffffu, d2, o);
            d3 += __shfl_down_sync(0xffffffffu, d3, o);
            d4 += __shfl_down_sync(0xffffffffu, d4, o);
        }
        if (ln == 0) {
            float iq = 1.0f / fmaxf(sqrtf(ss), 1e-12f);
            float* o = out + ((size_t)b * NQ + q) * NW;
            o[0] = d0 * iq; o[1] = d1 * iq; o[2] = d2 * iq; o[3] = d3 * iq; o[4] = d4 * iq;
        }
    }
}

extern "C" void kernel_launch(void* const* d_in, const int* in_sizes, int n_in,
                              void* d_out, int out_size) {
    const float* ftest  = (const float*)d_in[0];
    const float* ftrain = (const float*)d_in[1];
    const int* usp = (n_in > 4) ? (const int*)d_in[4] : nullptr;
    int B = in_sizes[1] / (NS * DIM);
    if (B > MAXB) B = MAXB;
    if (B < 1) B = 1;
    k_prep<<<2 * B, 256>>>(ftrain, usp);
    k_qp<<<B, TQP>>>();
    k_out<<<5 * B, 160>>>(ftest, usp, (float*)d_out);
}

// round 13
// speedup vs baseline: 4.0158x; 1.6591x over previous
#include <cuda_runtime.h>
#include <cuda_bf16.h>
#include <math.h>

#define NS   25      // n_shot * n_way (support samples)
#define NW   5       // n_way
#define NV   125     // QP variables
#define DIM  640
#define NQ   75
#define MAXB 512
#define TQP  160     // 5 warps for fused qp kernel
#define HD   320     // dim chunk for k_prep

// ------------------- global scratch (static, no allocations) -------------------
__device__ float g_ftu[(size_t)MAXB * NS * DIM];     // transformed (unnormalized) train feats
__device__ float g_Kp[(size_t)2 * MAXB * NS * NS];   // partial raw Gram (per dim-chunk)

// ------------------- simple_transform -------------------
__device__ __forceinline__ float simp_g(float u) {
    float t = __logf(__fdividef(1.0f, u + 1e-5f) + 1.0f);
    return __powf(t, -1.3f);
}
__device__ __forceinline__ float simp(float x, float c0) {
    float g = simp_g(fabsf(x));
    return (x >= 0.0f) ? (g - c0) : (c0 - g);
}

// =====================================================================
// Kernel 1: transform train chunk + partial raw Gram.
// Gram via 2-row register blocking: warp holds rows (2t, 2t+1) in regs,
// streams each partner row ONCE from smem -> ~4x less LDS traffic.
// grid = 2*B  (blockIdx.x = b*2 + chunk)
// =====================================================================
__global__ void __launch_bounds__(256) k_prep(const float* __restrict__ ftrain,
                                              const int* __restrict__ usp) {
    __shared__ __align__(16) float tile[NS * HD];   // 32 KB
    int bb = blockIdx.x, b = bb >> 1, ch = bb & 1;
    int tid = threadIdx.x;
    int us = usp ? (usp[0] != 0) : 1;
    float c0 = simp_g(0.0f);

    const float* fbase = ftrain + (size_t)b * NS * DIM + ch * HD;
    float* obase = g_ftu + (size_t)b * NS * DIM + ch * HD;

    // transform: float4 path, 25*80 float4
    for (int e = tid; e < NS * 80; e += 256) {
        int r = e / 80, c = e - r * 80;
        float4 v = ((const float4*)(fbase + r * DIM))[c];
        if (us) {
            v.x = simp(v.x, c0); v.y = simp(v.y, c0);
            v.z = simp(v.z, c0); v.w = simp(v.w, c0);
        }
        ((float4*)tile)[r * 80 + c] = v;
        ((float4*)(obase + r * DIM))[c] = v;
    }
    __syncthreads();

    int wp = tid >> 5, ln = tid & 31;
    float* Kout = g_Kp + ((size_t)ch * MAXB + b) * (NS * NS);
    // block t<12: rows (2t, 2t+1); block 12: row 24 alone.
    // per-warp tasks balanced (~38-49 dots each)
    const signed char T0[8] = {0, 1, 2, 3, 4, 5, 6, 7};
    const signed char T1[8] = {-1, -1, -1, 12, 11, 10, 9, 8};
    #pragma unroll 1
    for (int sel = 0; sel < 2; sel++) {
        int t = sel ? T1[wp] : T0[wp];
        if (t < 0) continue;
        if (t < 12) {
            int r0 = 2 * t;
            float a0[10], a1[10];
            #pragma unroll
            for (int k = 0; k < 10; k++) a0[k] = tile[r0 * HD + k * 32 + ln];
            #pragma unroll
            for (int k = 0; k < 10; k++) a1[k] = tile[(r0 + 1) * HD + k * 32 + ln];
            // intra-block dots
            float s00 = 0, s01 = 0, s11 = 0;
            #pragma unroll
            for (int k = 0; k < 10; k++) {
                s00 = fmaf(a0[k], a0[k], s00);
                s01 = fmaf(a0[k], a1[k], s01);
                s11 = fmaf(a1[k], a1[k], s11);
            }
            #pragma unroll
            for (int o = 16; o; o >>= 1) {
                s00 += __shfl_down_sync(0xffffffffu, s00, o);
                s01 += __shfl_down_sync(0xffffffffu, s01, o);
                s11 += __shfl_down_sync(0xffffffffu, s11, o);
            }
            if (ln == 0) {
                Kout[r0 * NS + r0] = s00;
                Kout[r0 * NS + r0 + 1] = s01;
                Kout[(r0 + 1) * NS + r0] = s01;
                Kout[(r0 + 1) * NS + r0 + 1] = s11;
            }
            // cross dots: stream each partner row once
            for (int c = r0 + 2; c < NS; c++) {
                float d0 = 0, d1 = 0;
                #pragma unroll
                for (int k = 0; k < 10; k++) {
                    float v = tile[c * HD + k * 32 + ln];
                    d0 = fmaf(a0[k], v, d0);
                    d1 = fmaf(a1[k], v, d1);
                }
                #pragma unroll
                for (int o = 16; o; o >>= 1) {
                    d0 += __shfl_down_sync(0xffffffffu, d0, o);
                    d1 += __shfl_down_sync(0xffffffffu, d1, o);
                }
                if (ln == 0) {
                    Kout[r0 * NS + c] = d0;       Kout[c * NS + r0] = d0;
                    Kout[(r0 + 1) * NS + c] = d1; Kout[c * NS + r0 + 1] = d1;
                }
            }
        } else {
            // row 24 self-dot
            float s = 0;
            #pragma unroll
            for (int k = 0; k < 10; k++) {
                float v = tile[24 * HD + k * 32 + ln];
                s = fmaf(v, v, s);
            }
            #pragma unroll
            for (int o = 16; o; o >>= 1) s += __shfl_down_sync(0xffffffffu, s, o);
            if (ln == 0) Kout[24 * NS + 24] = s;
        }
    }
}

// =====================================================================
// Kernel 2 (FUSED): QP via IPM + W epilogue + query projection.
// One CTA (5 warps) per batch element.  W overlays Hinv/Smat (dead after QP).
// =====================================================================
struct QPShared {
    union {
        struct { float Hinv[NW][625]; float Smat[625]; } f;   // 3750 floats
        __align__(16) float W[NW * DIM];                       // 3200 floats
    } u;
    float M[625];
    float Sinv[625];
    float x[NV], s_[NV], z_[NV], bestx[NV], d_[NV];
    float rx[NV], rz[NV], r1[NV], uv[NV], rsc[NV];
    float dxa[NV], dsa[NV], dza[NV];
    float dxc[NV], dsc[NV], dzc[NV];
    float y_[NS], ry[NS], gvec[NS], dya[NS], dyc[NS];
    float inv[NS];
    float red[8];
    float red4[NW][4];
};

__device__ __forceinline__ float blk_sum5(float v, volatile float* red) {
    int tid = threadIdx.x;
    __syncthreads();
    #pragma unroll
    for (int o = 16; o; o >>= 1) v += __shfl_down_sync(0xffffffffu, v, o);
    if ((tid & 31) == 0) red[tid >> 5] = v;
    __syncthreads();
    return red[0] + red[1] + red[2] + red[3] + red[4];
}
__device__ __forceinline__ float blk_min5(float v, volatile float* red) {
    int tid = threadIdx.x;
    __syncthreads();
    #pragma unroll
    for (int o = 16; o; o >>= 1) v = fminf(v, __shfl_down_sync(0xffffffffu, v, o));
    if ((tid & 31) == 0) red[tid >> 5] = v;
    __syncthreads();
    return fminf(fminf(fminf(red[0], red[1]), fminf(red[2], red[3])), red[4]);
}

// In-place Gauss-Jordan inverse of 25x25, row-per-lane in registers.
// Warp-uniform control flow; lanes 25-31 carry garbage, never stored.
__device__ __forceinline__ void gj25(float* a, int ln) {
    #pragma unroll
    for (int j = 0; j < NS; j++) {
        float f = a[j];
        float piv = __shfl_sync(0xffffffffu, f, j);
        float ip = 1.0f / piv;
        bool isj = (ln == j);
        #pragma unroll
        for (int k = 0; k < NS; k++) {
            if (k == j) continue;
            float r = __shfl_sync(0xffffffffu, a[k], j) * ip;
            float upd = fmaf(-f, r, a[k]);
            a[k] = isj ? r : upd;
        }
        a[j] = isj ? ip : (-f * ip);
    }
}

// Hinv_w = (M + diag(d_w))^{-1} per warp; Sinv = (sum_w Hinv_w)^{-1} (warp0).
__device__ __noinline__ void factorize(QPShared& S) {
    int tid = threadIdx.x, wp = tid >> 5, ln = tid & 31;
    float a[NS];
    if (ln < NS) {
        #pragma unroll
        for (int k = 0; k < NS; k++) a[k] = S.M[ln * NS + k];
        a[ln] += S.d_[ln * NW + wp];
    }
    gj25(a, ln);
    if (ln < NS) {
        #pragma unroll
        for (int k = 0; k < NS; k++) S.u.f.Hinv[wp][ln * NS + k] = a[k];
    }
    __syncthreads();
    for (int e = tid; e < 625; e += TQP)
        S.u.f.Smat[e] = S.u.f.Hinv[0][e] + S.u.f.Hinv[1][e] + S.u.f.Hinv[2][e]
                      + S.u.f.Hinv[3][e] + S.u.f.Hinv[4][e];
    __syncthreads();
    if (wp == 0) {
        if (ln < NS) {
            #pragma unroll
            for (int k = 0; k < NS; k++) a[k] = S.u.f.Smat[ln * NS + k];
        }
        gj25(a, ln);
        if (ln < NS) {
            #pragma unroll
            for (int k = 0; k < NS; k++) S.Sinv[ln * NS + k] = a[k];
        }
    }
    __syncthreads();
}

// KKT apply: NULL pointer == zero vector.
__device__ __noinline__ void applyKKT(QPShared& S, const float* rx, const float* rs,
                                      const float* rz, const float* ry,
                                      float* dx, float* ds, float* dz, float* dy) {
    int tid = threadIdx.x, wp = tid >> 5, ln = tid & 31;
    if (tid < NV) {
        float rxv = rx ? rx[tid] : 0.0f;
        float rsv = rs ? rs[tid] : 0.0f;
        float rzv = rz ? rz[tid] : 0.0f;
        S.r1[tid] = -rxv - S.d_[tid] * rzv + rsv;
    }
    __syncthreads();
    if (ln < NS) {                      // u_w = H_w^{-1} r1_w
        const float* Hi = S.u.f.Hinv[wp] + ln * NS;
        float acc = 0.0f;
        #pragma unroll
        for (int j = 0; j < NS; j++) acc = fmaf(Hi[j], S.r1[j * NW + wp], acc);
        S.uv[ln * NW + wp] = acc;
    }
    __syncthreads();
    if (tid < NS) {
        float g = S.uv[tid * NW] + S.uv[tid * NW + 1] + S.uv[tid * NW + 2]
                + S.uv[tid * NW + 3] + S.uv[tid * NW + 4];
        if (ry) g += ry[tid];
        S.gvec[tid] = g;
    }
    __syncthreads();
    if (wp == 0 && ln < NS) {           // dy = S_y^{-1} g
        const float* Si = S.Sinv + ln * NS;
        float acc = 0.0f;
        #pragma unroll
        for (int j = 0; j < NS; j++) acc = fmaf(Si[j], S.gvec[j], acc);
        dy[ln] = acc;
    }
    __syncthreads();
    if (ln < NS) {                      // dx = u - H^{-1} A^T dy
        const float* Hi = S.u.f.Hinv[wp] + ln * NS;
        float acc = 0.0f;
        #pragma unroll
        for (int j = 0; j < NS; j++) acc = fmaf(Hi[j], dy[j], acc);
        dx[ln * NW + wp] = S.uv[ln * NW + wp] - acc;
    }
    __syncthreads();
    if (tid < NV) {
        float rsv = rs ? rs[tid] : 0.0f;
        float rzv = rz ? rz[tid] : 0.0f;
        float dxv = dx[tid];
        dz[tid] = S.d_[tid] * (dxv + rzv) - rsv;
        ds[tid] = -dxv - rzv;
    }
}

__global__ void __launch_bounds__(TQP) k_fused(const float* __restrict__ ftest,
                                               const int* __restrict__ usp,
                                               float* __restrict__ out) {
    __shared__ QPShared S;
    int b = blockIdx.x, tid = threadIdx.x;
    int wp = tid >> 5, ln = tid & 31;
    int us = usp ? (usp[0] != 0) : 1;
    float c0 = simp_g(0.0f);

    for (int e = tid; e < 625; e += TQP)
        S.M[e] = g_Kp[(size_t)b * 625 + e] + g_Kp[((size_t)MAXB + b) * 625 + e];
    __syncthreads();
    if (tid < NS)
        S.inv[tid] = 1.0f / fmaxf(sqrtf(S.M[tid * NS + tid]), 1e-12f);
    __syncthreads();
    for (int e = tid; e < 625; e += TQP) {
        int r = e / NS, c = e - r * NS;
        S.M[e] = S.M[e] * S.inv[r] * S.inv[c] + ((r == c) ? 1.0f : 0.0f);
    }
    if (tid < NV) {
        S.d_[tid] = 1.0f;
        int sidx = tid / NW, w = tid - sidx * NW;
        float oh = ((sidx % NW) == w) ? 1.0f : 0.0f;
        S.rx[tid] = -oh;          // p
        S.rz[tid] = -0.1f * oh;   // -h
    }
    __syncthreads();
    factorize(S);
    applyKKT(S, S.rx, nullptr, S.rz, nullptr, S.x, S.s_, S.z_, S.y_);
    float mv = (tid < NV) ? S.s_[tid] : 3.0e38f;
    float m = blk_min5(mv, S.red);
    if (tid < NV && m < 0.0f) S.s_[tid] -= (m - 1.0f);
    mv = (tid < NV) ? S.z_[tid] : 3.0e38f;
    m = blk_min5(mv, S.red);
    if (tid < NV && m < 0.0f) S.z_[tid] -= (m - 1.0f);
    __syncthreads();

    float best_res = 3.0e38f;
    for (int it = 0; it < 3; it++) {
        if (ln < NS) {
            const float* Mr = S.M + ln * NS;
            float qx = 0.0f;
            #pragma unroll
            for (int j = 0; j < NS; j++) qx = fmaf(Mr[j], S.x[j * NW + wp], qx);
            int v = ln * NW + wp;
            float oh = ((ln % NW) == wp) ? 1.0f : 0.0f;
            S.rx[v] = S.y_[ln] + S.z_[v] + qx - oh;
            S.rz[v] = S.x[v] + S.s_[v] - 0.1f * oh;
        }
        if (tid < NS)
            S.ry[tid] = S.x[tid * NW] + S.x[tid * NW + 1] + S.x[tid * NW + 2]
                      + S.x[tid * NW + 3] + S.x[tid * NW + 4];
        __syncthreads();
        // fused 4-way reduction: sz, |rx|^2, |rz|^2, |ry|^2
        float v0 = (tid < NV) ? S.s_[tid] * S.z_[tid] : 0.0f;
        float v1 = (tid < NV) ? S.rx[tid] * S.rx[tid] : 0.0f;
        float v2 = (tid < NV) ? S.rz[tid] * S.rz[tid] : 0.0f;
        float v3 = (tid < NS) ? S.ry[tid] * S.ry[tid] : 0.0f;
        #pragma unroll
        for (int o = 16; o; o >>= 1) {
            v0 += __shfl_down_sync(0xffffffffu, v0, o);
            v1 += __shfl_down_sync(0xffffffffu, v1, o);
            v2 += __shfl_down_sync(0xffffffffu, v2, o);
            v3 += __shfl_down_sync(0xffffffffu, v3, o);
        }
        if (ln == 0) {
            S.red4[wp][0] = v0; S.red4[wp][1] = v1;
            S.red4[wp][2] = v2; S.red4[wp][3] = v3;
        }
        __syncthreads();
        float sz  = S.red4[0][0] + S.red4[1][0] + S.red4[2][0] + S.red4[3][0] + S.red4[4][0];
        float nrx = sqrtf(S.red4[0][1] + S.red4[1][1] + S.red4[2][1] + S.red4[3][1] + S.red4[4][1] + 1e-30f);
        float nrz = sqrtf(S.red4[0][2] + S.red4[1][2] + S.red4[2][2] + S.red4[3][2] + S.red4[4][2] + 1e-30f);
        float nry = sqrtf(S.red4[0][3] + S.red4[1][3] + S.red4[2][3] + S.red4[3][3] + S.red4[4][3] + 1e-30f);
        float mu = fabsf(sz) * (1.0f / 125.0f);
        float res = nrz + nry + nrx + 125.0f * mu;
        if (res < best_res) { best_res = res; if (tid < NV) S.bestx[tid] = S.x[tid]; }
        if (it == 2) break;

        if (tid < NV) S.d_[tid] = S.z_[tid] / S.s_[tid];
        __syncthreads();
        factorize(S);
        applyKKT(S, S.rx, S.z_, S.rz, S.ry, S.dxa, S.dsa, S.dza, S.dya);
        float az = (tid < NV) ? ((S.dza[tid] < 0.0f) ? -S.z_[tid] / S.dza[tid] : 1e12f) : 1e12f;
        float as = (tid < NV) ? ((S.dsa[tid] < 0.0f) ? -S.s_[tid] / S.dsa[tid] : 1e12f) : 1e12f;
        float alpha = fminf(blk_min5(fminf(az, as), S.red), 1.0f);
        float tt = (tid < NV) ? (S.s_[tid] + alpha * S.dsa[tid]) * (S.z_[tid] + alpha * S.dza[tid]) : 0.0f;
        float sumt = blk_sum5(tt, S.red);
        float ratio = sumt / sz;
        float musig = mu * ratio * ratio * ratio;
        if (tid < NV) S.rsc[tid] = (-musig + S.dsa[tid] * S.dza[tid]) / S.s_[tid];
        __syncthreads();
        applyKKT(S, nullptr, S.rsc, nullptr, nullptr, S.dxc, S.dsc, S.dzc, S.dyc);
        __syncthreads();
        if (tid < NV) { S.dxa[tid] += S.dxc[tid]; S.dsa[tid] += S.dsc[tid]; S.dza[tid] += S.dzc[tid]; }
        if (tid < NS) S.dya[tid] += S.dyc[tid];
        az = (tid < NV) ? ((S.dza[tid] < 0.0f) ? -S.z_[tid] / S.dza[tid] : 1e12f) : 1e12f;
        as = (tid < NV) ? ((S.dsa[tid] < 0.0f) ? -S.s_[tid] / S.dsa[tid] : 1e12f) : 1e12f;
        alpha = fminf(0.999f * blk_min5(fminf(az, as), S.red), 1.0f);
        if (tid < NV) {
            S.x[tid]  += alpha * S.dxa[tid];
            S.s_[tid] += alpha * S.dsa[tid];
            S.z_[tid] += alpha * S.dza[tid];
        }
        if (tid < NS) S.y_[tid] += alpha * S.dya[tid];
        __syncthreads();
    }

    // ---- epilogue 1: W = (bestx * invn)^T ftu, into smem (overlays Hinv/Smat) ----
    if (tid < NV) S.x[tid] = S.bestx[tid] * S.inv[tid / NW];
    __syncthreads();
    {
        const float4* fu4 = (const float4*)(g_ftu + (size_t)b * NS * DIM);
        int d4 = tid;                    // exactly 160 float4-columns, 1 per thread
        float4 acc[NW];
        #pragma unroll
        for (int w = 0; w < NW; w++) acc[w] = make_float4(0.f, 0.f, 0.f, 0.f);
        #pragma unroll
        for (int s = 0; s < NS; s++) {
            float4 fv = fu4[s * 160 + d4];
            #pragma unroll
            for (int w = 0; w < NW; w++) {
                float xw = S.x[s * NW + w];
                acc[w].x = fmaf(xw, fv.x, acc[w].x);
                acc[w].y = fmaf(xw, fv.y, acc[w].y);
                acc[w].z = fmaf(xw, fv.z, acc[w].z);
                acc[w].w = fmaf(xw, fv.w, acc[w].w);
            }
        }
        #pragma unroll
        for (int w = 0; w < NW; w++)
            ((float4*)(S.u.W + w * DIM))[d4] = acc[w];
    }
    __syncthreads();

    // ---- epilogue 2: stream this batch's 75 queries (15 per warp) ----
    const float* fq = ftest + (size_t)b * NQ * DIM;
    #pragma unroll 1
    for (int qq = 0; qq < 15; qq++) {
        int q = wp * 15 + qq;
        const float4* row4 = (const float4*)(fq + (size_t)q * DIM);
        float ss = 0, d0 = 0, d1 = 0, d2 = 0, d3 = 0, d4v = 0;
        #pragma unroll
        for (int j = 0; j < 5; j++) {
            int i4 = ln + 32 * j;
            float4 v = row4[i4];
            if (us) {
                v.x = simp(v.x, c0); v.y = simp(v.y, c0);
                v.z = simp(v.z, c0); v.w = simp(v.w, c0);
            }
            ss = fmaf(v.x, v.x, fmaf(v.y, v.y, fmaf(v.z, v.z, fmaf(v.w, v.w, ss))));
            float4 w0 = ((const float4*)(S.u.W + 0 * DIM))[i4];
            float4 w1 = ((const float4*)(S.u.W + 1 * DIM))[i4];
            float4 w2 = ((const float4*)(S.u.W + 2 * DIM))[i4];
            float4 w3 = ((const float4*)(S.u.W + 3 * DIM))[i4];
            float4 w4 = ((const float4*)(S.u.W + 4 * DIM))[i4];
            d0 = fmaf(w0.x, v.x, fmaf(w0.y, v.y, fmaf(w0.z, v.z, fmaf(w0.w, v.w, d0))));
            d1 = fmaf(w1.x, v.x, fmaf(w1.y, v.y, fmaf(w1.z, v.z, fmaf(w1.w, v.w, d1))));
            d2 = fmaf(w2.x, v.x, fmaf(w2.y, v.y, fmaf(w2.z, v.z, fmaf(w2.w, v.w, d2))));
            d3 = fmaf(w3.x, v.x, fmaf(w3.y, v.y, fmaf(w3.z, v.z, fmaf(w3.w, v.w, d3))));
            d4v = fmaf(w4.x, v.x, fmaf(w4.y, v.y, fmaf(w4.z, v.z, fmaf(w4.w, v.w, d4v))));
        }
        #pragma unroll
        for (int o = 16; o; o >>= 1) {
            ss  += __shfl_down_sync(0xffffffffu, ss, o);
            d0  += __shfl_down_sync(0xffffffffu, d0, o);
            d1  += __shfl_down_sync(0xffffffffu, d1, o);
            d2  += __shfl_down_sync(0xffffffffu, d2, o);
            d3  += __shfl_down_sync(0xffffffffu, d3, o);
            d4v += __shfl_down_sync(0xffffffffu, d4v, o);
        }
        if (ln == 0) {
            float iq = 1.0f / fmaxf(sqrtf(ss), 1e-12f);
            float* o = out + ((size_t)b * NQ + q) * NW;
            o[0] = d0 * iq; o[1] = d1 * iq; o[2] = d2 * iq; o[3] = d3 * iq; o[4] = d4v * iq;
        }
    }
}

extern "C" void kernel_launch(void* const* d_in, const int* in_sizes, int n_in,
                              void* d_out, int out_size) {
    const float* ftest  = (const float*)d_in[0];
    const float* ftrain = (const float*)d_in[1];
    const int* usp = (n_in > 4) ? (const int*)d_in[4] : nullptr;
    int B = in_sizes[1] / (NS * DIM);
    if (B > MAXB) B = MAXB;
    if (B < 1) B = 1;
    k_prep<<<2 * B, 256>>>(ftrain, usp);
    k_fused<<<B, TQP>>>(ftest, usp, (float*)d_out);
}